// round 15
// baseline (speedup 1.0000x reference)
#include <cuda_runtime.h>
#include <cstdint>
#include <cstddef>

#define TDIM 512
#define BDIM 128
#define EDIM 128
#define SDIM 1024
#define NLEV 10
#define PBSTRIDE (NLEV * TDIM)
#define NCH 16
#define CHT 32
#define INFV 3.0e38f

typedef unsigned long long ull;

// ---------------- device scratch ----------------
__device__ float g_cTB[TDIM * BDIM];        // [t][b] u - TP
__device__ float g_t0T[BDIM * TDIM];        // [b][tau]
__device__ float g_TPT[BDIM * TDIM];        // [b][tau]
__device__ float g_t0TB[TDIM * BDIM];       // [tau][b]
__device__ float g_TPTB[TDIM * BDIM];       // [tau][b]
__device__ float g_P[BDIM * PBSTRIDE];      // [b][k][tau] sparse min table
__device__ float g_Pt[NLEV * TDIM * BDIM];  // [k][tau][b]
__device__ float g_m[SDIM * TDIM];          // [j][t] scalar m
__device__ ull   g_mp[SDIM * TDIM];         // [j][t] packed (m,m)
__device__ int   g_js[TDIM];                // first j with m>0
__device__ float g_A[NCH * BDIM];
__device__ float g_B[NCH * BDIM];

// ---------------- packed f32x2 helpers ----------------
__device__ __forceinline__ ull ffma2(ull a, ull b, ull c) {
    ull d;
    asm("fma.rn.f32x2 %0, %1, %2, %3;" : "=l"(d) : "l"(a), "l"(b), "l"(c));
    return d;
}
__device__ __forceinline__ ull pack2(float x) {
    ull d;
    asm("mov.b64 %0, {%1, %2};" : "=l"(d) : "f"(x), "f"(x));
    return d;
}
__device__ __forceinline__ void unpack2(ull v, float& lo, float& hi) {
    asm("mov.b64 {%0, %1}, %2;" : "=f"(lo), "=f"(hi) : "l"(v));
}

// ---------------- K_A: per-chunk scan composition + g_mp zeroing ---------
__global__ __launch_bounds__(256) void k_A(const float* __restrict__ d1,
                                           const float* __restrict__ d2,
                                           const float* __restrict__ u) {
    int c = blockIdx.x, tid = threadIdx.x;
    if (tid < BDIM) {
        int b = tid;
        float A = 0.f, Bv = 0.f;
        int t0 = c * CHT;
#pragma unroll 4
        for (int t = t0; t < t0 + CHT; ++t) {
            float x = d1[t * BDIM + b] + d2[t * BDIM + b] - u[t * BDIM + b];
            A += x;
            Bv = fmaxf(Bv + x, 0.f);
        }
        g_A[c * BDIM + b] = A;
        g_B[c * BDIM + b] = Bv;
    } else {
        int z = c * 128 + (tid - 128);  // 0..2047
        ulonglong2* p = (ulonglong2*)g_mp;
        const int n = SDIM * TDIM / 2;
        ulonglong2 zz; zz.x = 0ull; zz.y = 0ull;
        for (int i = z; i < n; i += NCH * 128) p[i] = zz;
    }
}

// ---------------- K_B: fused prefix-compose + walk + emit + sparse table -
__global__ __launch_bounds__(256) void k_B(const float* __restrict__ d1,
                                           const float* __restrict__ d2,
                                           const float* __restrict__ u) {
    int b = blockIdx.x, tid = threadIdx.x;
    __shared__ float s0[TDIM], s1[TDIM];

    if (tid < NCH) {
        float L = 0.f;
        for (int k = 0; k < tid; ++k)
            L = fmaxf(L + g_A[k * BDIM + b], g_B[k * BDIM + b]);
        int t0 = tid * CHT;
        float* t0Trow = g_t0T + (size_t)b * TDIM;
        float* TPTrow = g_TPT + (size_t)b * TDIM;
        float* Prow = g_P + (size_t)b * PBSTRIDE;
#pragma unroll 4
        for (int t = t0; t < t0 + CHT; ++t) {
            float a1 = d1[t * BDIM + b];
            float a2 = d2[t * BDIM + b];
            float uu = u[t * BDIM + b];
            float top0 = L + a1;
            float TP = top0 + a2;
            g_t0TB[t * BDIM + b] = top0;
            g_TPTB[t * BDIM + b] = TP;
            g_cTB[t * BDIM + b] = uu - TP;
            t0Trow[t] = top0;
            TPTrow[t] = TP;
            L = fmaxf(TP - uu, 0.f);
            s0[t] = L;
            Prow[t] = L;
            g_Pt[(size_t)t * BDIM + b] = L;
        }
    }
    __syncthreads();

    float* base = g_P + (size_t)b * PBSTRIDE;
    float* cur = s0;
    float* nxt = s1;
    for (int k = 1; k < NLEV; ++k) {
        int h = 1 << (k - 1);
#pragma unroll
        for (int i = 0; i < 2; ++i) {
            int tau = tid + i * 256;
            float v = cur[tau];
            if (tau + h < TDIM) v = fminf(v, cur[tau + h]);
            nxt[tau] = v;
            base[k * TDIM + tau] = v;
            g_Pt[((size_t)k * TDIM + tau) * BDIM + b] = v;
        }
        __syncthreads();
        float* tmp = cur; cur = nxt; nxt = tmp;
    }
}

// ---------------- K3: m[t][j] = max_b (c + C_j)  (+ fused j* search) -----
__global__ __launch_bounds__(256) void k_m() {
    int t = blockIdx.x, tid = threadIdx.x;
    const float* cc = g_cTB + (size_t)t * BDIM;
    __shared__ int sjs;
    if (tid == 0) sjs = 2 * t + 2;
    __syncthreads();

    for (int tau = tid; tau <= t; tau += 256) {
        int n = t - tau;
        float me = -INFV, mo = -INFV;
        const float* a0 = g_t0TB + (size_t)tau * BDIM;
        const float* p0 = g_TPTB + (size_t)tau * BDIM;
        if (n) {
            int k = 31 - __clz(n);
            const float* r1 = g_Pt + ((size_t)k * TDIM + tau) * BDIM;
            const float* r2 = g_Pt + ((size_t)k * TDIM + (t - (1 << k))) * BDIM;
#pragma unroll 4
            for (int b4 = 0; b4 < BDIM; b4 += 4) {
                float4 A = *(const float4*)(a0 + b4);
                float4 P = *(const float4*)(p0 + b4);
                float4 C = *(const float4*)(cc + b4);
                float4 X = *(const float4*)(r1 + b4);
                float4 Y = *(const float4*)(r2 + b4);
                float Rx = fminf(X.x, Y.x), Ry = fminf(X.y, Y.y);
                float Rz = fminf(X.z, Y.z), Rw = fminf(X.w, Y.w);
                me = fmaxf(me, fmaxf(fmaxf(C.x + fminf(A.x, Rx), C.y + fminf(A.y, Ry)),
                                     fmaxf(C.z + fminf(A.z, Rz), C.w + fminf(A.w, Rw))));
                mo = fmaxf(mo, fmaxf(fmaxf(C.x + fminf(P.x, Rx), C.y + fminf(P.y, Ry)),
                                     fmaxf(C.z + fminf(P.z, Rz), C.w + fminf(P.w, Rw))));
            }
        } else {
#pragma unroll 4
            for (int b4 = 0; b4 < BDIM; b4 += 4) {
                float4 A = *(const float4*)(a0 + b4);
                float4 P = *(const float4*)(p0 + b4);
                float4 C = *(const float4*)(cc + b4);
                me = fmaxf(me, fmaxf(fmaxf(C.x + A.x, C.y + A.y),
                                     fmaxf(C.z + A.z, C.w + A.w)));
                mo = fmaxf(mo, fmaxf(fmaxf(C.x + P.x, C.y + P.y),
                                     fmaxf(C.z + P.z, C.w + P.w)));
            }
        }
        g_m[(size_t)(2 * tau) * TDIM + t] = me;
        g_m[(size_t)(2 * tau + 1) * TDIM + t] = mo;
        g_mp[(size_t)(2 * tau) * TDIM + t] = pack2(me);
        g_mp[(size_t)(2 * tau + 1) * TDIM + t] = pack2(mo);
        if (me > 0.f) atomicMin(&sjs, 2 * tau);
        else if (mo > 0.f) atomicMin(&sjs, 2 * tau + 1);
    }
    __syncthreads();
    if (tid == 0) g_js[t] = sjs;
}

// ---------------- K4: GEMM, 512 threads, 4x8 thread tile, fused corr -----
// CTA = (128 t-rows tile) x (batch b). 512 threads: 4 rows x 8 cols each.
__global__ __launch_bounds__(512, 2) void k_gemm(const float* __restrict__ v1,
                                                 const float* __restrict__ v2,
                                                 float* __restrict__ out) {
    int b = blockIdx.x;
    int tile = 3 - blockIdx.y;  // heavy tiles first
    int t0 = tile * 128;
    int tid = threadIdx.x;
    int rg = tid >> 4, cg = tid & 15;   // rg 0..31, cg 0..15
    int r0 = rg * 4, e0 = cg * 8;

    __shared__ float sV[2][16][EDIM];   // 16 KB
    __shared__ ull sMp[2][16][128];     // 32 KB

    ull acc[4][4];
#pragma unroll
    for (int i = 0; i < 4; ++i)
#pragma unroll
        for (int j = 0; j < 4; ++j) acc[i][j] = 0ull;

    int nst = 16 * (tile + 1);

    // staging: one float4 (V) + 2 ulonglong2 (W) per thread
    int vs = tid >> 5, ve = (tid & 31) * 4;   // V row s=vs (0..15), 4 floats
    int ws = tid >> 5, wt = (tid & 31) * 4;   // W row s=ws, 4 ull

    float4 rv;
    ulonglong2 rw[2];

    auto load_stage = [&](int st) {
        int j0 = st * 16;
        int j = j0 + vs;
        const float* src = (j & 1) ? v2 : v1;
        rv = *(const float4*)&src[((size_t)(j >> 1) * BDIM + b) * EDIM + ve];
        const ull* wsrc = &g_mp[(size_t)(j0 + ws) * TDIM + t0 + wt];
        rw[0] = *(const ulonglong2*)wsrc;
        rw[1] = *(const ulonglong2*)(wsrc + 2);
    };
    auto store_stage = [&](int bf) {
        *(float4*)&sV[bf][vs][ve] = rv;
        *(ulonglong2*)&sMp[bf][ws][wt] = rw[0];
        *(ulonglong2*)&sMp[bf][ws][wt + 2] = rw[1];
    };

    load_stage(0);
    for (int st = 0; st < nst; ++st) {
        int bf = st & 1;
        store_stage(bf);
        __syncthreads();
        if (st + 1 < nst) load_stage(st + 1);
#pragma unroll
        for (int s = 0; s < 16; ++s) {
            ulonglong2 vv0 = *(const ulonglong2*)&sV[bf][s][e0];
            ulonglong2 vv1 = *(const ulonglong2*)&sV[bf][s][e0 + 4];
            ull va0 = vv0.x, va1 = vv0.y, va2 = vv1.x, va3 = vv1.y;
#pragma unroll
            for (int h = 0; h < 2; ++h) {
                ulonglong2 wp = *(const ulonglong2*)&sMp[bf][s][r0 + 2 * h];
                acc[2 * h][0] = ffma2(wp.x, va0, acc[2 * h][0]);
                acc[2 * h][1] = ffma2(wp.x, va1, acc[2 * h][1]);
                acc[2 * h][2] = ffma2(wp.x, va2, acc[2 * h][2]);
                acc[2 * h][3] = ffma2(wp.x, va3, acc[2 * h][3]);
                acc[2 * h + 1][0] = ffma2(wp.y, va0, acc[2 * h + 1][0]);
                acc[2 * h + 1][1] = ffma2(wp.y, va1, acc[2 * h + 1][1]);
                acc[2 * h + 1][2] = ffma2(wp.y, va2, acc[2 * h + 1][2]);
                acc[2 * h + 1][3] = ffma2(wp.y, va3, acc[2 * h + 1][3]);
            }
        }
    }

    // ---- fused banded correction + store: out = acc - relu(m - s_b) * V ----
    const float* Pb = g_P + (size_t)b * PBSTRIDE;
    const float* t0b = g_t0T + (size_t)b * TDIM;
    const float* tpb = g_TPT + (size_t)b * TDIM;

#pragma unroll
    for (int i = 0; i < 4; ++i) {
        int t = t0 + r0 + i;
        float r[8];
#pragma unroll
        for (int j = 0; j < 4; ++j) unpack2(acc[i][j], r[2 * j], r[2 * j + 1]);

        int js = g_js[t];
        int tau0 = js >> 1;
        for (int tau = tau0; tau <= t; ++tau) {
            int n = t - tau;
            float R;
            if (n) {
                int k = 31 - __clz(n);
                R = fminf(Pb[k * TDIM + tau], Pb[k * TDIM + t - (1 << k)]);
            } else {
                R = INFV;
            }
            float Ca = fminf(t0b[tau], R);
            float Cp = fminf(tpb[tau], R);
            float Cm1 = tau ? fminf(tpb[tau - 1], fminf(Pb[tau - 1], R)) : 0.f;
            float s0 = Ca - Cm1;
            float s1 = Cp - Ca;
            float m0 = g_m[(size_t)(2 * tau) * TDIM + t];
            float m1 = g_m[(size_t)(2 * tau + 1) * TDIM + t];
            float c0 = fmaxf(m0 - s0, 0.f);
            float c1 = fmaxf(m1 - s1, 0.f);
            if (c0 > 0.f || c1 > 0.f) {
                const float* v1p = v1 + ((size_t)tau * BDIM + b) * EDIM + e0;
                const float* v2p = v2 + ((size_t)tau * BDIM + b) * EDIM + e0;
                float4 a0 = *(const float4*)v1p;
                float4 a1 = *(const float4*)(v1p + 4);
                float4 p0 = *(const float4*)v2p;
                float4 p1 = *(const float4*)(v2p + 4);
                r[0] -= c0 * a0.x + c1 * p0.x;
                r[1] -= c0 * a0.y + c1 * p0.y;
                r[2] -= c0 * a0.z + c1 * p0.z;
                r[3] -= c0 * a0.w + c1 * p0.w;
                r[4] -= c0 * a1.x + c1 * p1.x;
                r[5] -= c0 * a1.y + c1 * p1.y;
                r[6] -= c0 * a1.z + c1 * p1.z;
                r[7] -= c0 * a1.w + c1 * p1.w;
            }
        }

        size_t basei = ((size_t)t * BDIM + b) * EDIM + e0;
        *reinterpret_cast<float4*>(out + basei) = make_float4(r[0], r[1], r[2], r[3]);
        *reinterpret_cast<float4*>(out + basei + 4) = make_float4(r[4], r[5], r[6], r[7]);
    }
}

extern "C" void kernel_launch(void* const* d_in, const int* in_sizes, int n_in,
                              void* d_out, int out_size) {
    const float* v1 = (const float*)d_in[0];
    const float* v2 = (const float*)d_in[1];
    const float* d1 = (const float*)d_in[2];
    const float* d2 = (const float*)d_in[3];
    const float* u  = (const float*)d_in[4];
    float* out = (float*)d_out;

    k_A<<<NCH, 256>>>(d1, d2, u);         // 1
    k_B<<<BDIM, 256>>>(d1, d2, u);        // 2
    k_m<<<TDIM, 256>>>();                 // 3
    dim3 gm(BDIM, 4);
    k_gemm<<<gm, 512>>>(v1, v2, out);     // 4  <- ncu capture slot
}

// round 16
// speedup vs baseline: 2.0632x; 2.0632x over previous
#include <cuda_runtime.h>
#include <cstdint>
#include <cstddef>

#define TDIM 512
#define BDIM 128
#define EDIM 128
#define SDIM 1024
#define NLEV 10
#define PBSTRIDE (NLEV * TDIM)
#define NCH 16
#define CHT 32
#define INFV 3.0e38f

typedef unsigned long long ull;

// ---------------- device scratch ----------------
__device__ float g_cTB[TDIM * BDIM];        // [t][b] u - TP
__device__ float g_t0T[BDIM * TDIM];        // [b][tau]
__device__ float g_TPT[BDIM * TDIM];        // [b][tau]
__device__ float g_t0TB[TDIM * BDIM];       // [tau][b]
__device__ float g_TPTB[TDIM * BDIM];       // [tau][b]
__device__ float g_P[BDIM * PBSTRIDE];      // [b][k][tau] sparse min table
__device__ float g_Pt[NLEV * TDIM * BDIM];  // [k][tau][b]
__device__ float g_m[SDIM * TDIM];          // [j][t] scalar m
__device__ ull   g_mp[SDIM * TDIM];         // [j][t] packed (m,m)
__device__ int   g_js[TDIM];                // first j with m>0
__device__ float g_A[NCH * BDIM];
__device__ float g_B[NCH * BDIM];

// ---------------- packed f32x2 helpers ----------------
__device__ __forceinline__ ull ffma2(ull a, ull b, ull c) {
    ull d;
    asm("fma.rn.f32x2 %0, %1, %2, %3;" : "=l"(d) : "l"(a), "l"(b), "l"(c));
    return d;
}
__device__ __forceinline__ ull pack2(float x) {
    ull d;
    asm("mov.b64 %0, {%1, %2};" : "=l"(d) : "f"(x), "f"(x));
    return d;
}
__device__ __forceinline__ void unpack2(ull v, float& lo, float& hi) {
    asm("mov.b64 {%0, %1}, %2;" : "=f"(lo), "=f"(hi) : "l"(v));
}

// ---------------- K_A: per-chunk scan composition + g_mp zeroing ---------
__global__ __launch_bounds__(256) void k_A(const float* __restrict__ d1,
                                           const float* __restrict__ d2,
                                           const float* __restrict__ u) {
    int c = blockIdx.x, tid = threadIdx.x;
    if (tid < BDIM) {
        int b = tid;
        float A = 0.f, Bv = 0.f;
        int t0 = c * CHT;
#pragma unroll 4
        for (int t = t0; t < t0 + CHT; ++t) {
            float x = d1[t * BDIM + b] + d2[t * BDIM + b] - u[t * BDIM + b];
            A += x;
            Bv = fmaxf(Bv + x, 0.f);
        }
        g_A[c * BDIM + b] = A;
        g_B[c * BDIM + b] = Bv;
    } else {
        int z = c * 128 + (tid - 128);  // 0..2047
        ulonglong2* p = (ulonglong2*)g_mp;
        const int n = SDIM * TDIM / 2;
        ulonglong2 zz; zz.x = 0ull; zz.y = 0ull;
        for (int i = z; i < n; i += NCH * 128) p[i] = zz;
    }
}

// ---------------- K_B: fused prefix-compose + walk + emit + sparse table -
__global__ __launch_bounds__(256) void k_B(const float* __restrict__ d1,
                                           const float* __restrict__ d2,
                                           const float* __restrict__ u) {
    int b = blockIdx.x, tid = threadIdx.x;
    __shared__ float s0[TDIM], s1[TDIM];

    if (tid < NCH) {
        float L = 0.f;
        for (int k = 0; k < tid; ++k)
            L = fmaxf(L + g_A[k * BDIM + b], g_B[k * BDIM + b]);
        int t0 = tid * CHT;
        float* t0Trow = g_t0T + (size_t)b * TDIM;
        float* TPTrow = g_TPT + (size_t)b * TDIM;
        float* Prow = g_P + (size_t)b * PBSTRIDE;
#pragma unroll 4
        for (int t = t0; t < t0 + CHT; ++t) {
            float a1 = d1[t * BDIM + b];
            float a2 = d2[t * BDIM + b];
            float uu = u[t * BDIM + b];
            float top0 = L + a1;
            float TP = top0 + a2;
            g_t0TB[t * BDIM + b] = top0;
            g_TPTB[t * BDIM + b] = TP;
            g_cTB[t * BDIM + b] = uu - TP;
            t0Trow[t] = top0;
            TPTrow[t] = TP;
            L = fmaxf(TP - uu, 0.f);
            s0[t] = L;
            Prow[t] = L;
            g_Pt[(size_t)t * BDIM + b] = L;
        }
    }
    __syncthreads();

    float* base = g_P + (size_t)b * PBSTRIDE;
    float* cur = s0;
    float* nxt = s1;
    for (int k = 1; k < NLEV; ++k) {
        int h = 1 << (k - 1);
#pragma unroll
        for (int i = 0; i < 2; ++i) {
            int tau = tid + i * 256;
            float v = cur[tau];
            if (tau + h < TDIM) v = fminf(v, cur[tau + h]);
            nxt[tau] = v;
            base[k * TDIM + tau] = v;
            g_Pt[((size_t)k * TDIM + tau) * BDIM + b] = v;
        }
        __syncthreads();
        float* tmp = cur; cur = nxt; nxt = tmp;
    }
}

// ---------------- K3: m[t][j] = max_b (c + C_j)  (+ fused j* search) -----
__global__ __launch_bounds__(256) void k_m() {
    int t = blockIdx.x, tid = threadIdx.x;
    const float* cc = g_cTB + (size_t)t * BDIM;
    __shared__ int sjs;
    if (tid == 0) sjs = 2 * t + 2;
    __syncthreads();

    for (int tau = tid; tau <= t; tau += 256) {
        int n = t - tau;
        float me = -INFV, mo = -INFV;
        const float* a0 = g_t0TB + (size_t)tau * BDIM;
        const float* p0 = g_TPTB + (size_t)tau * BDIM;
        if (n) {
            int k = 31 - __clz(n);
            const float* r1 = g_Pt + ((size_t)k * TDIM + tau) * BDIM;
            const float* r2 = g_Pt + ((size_t)k * TDIM + (t - (1 << k))) * BDIM;
#pragma unroll 4
            for (int b4 = 0; b4 < BDIM; b4 += 4) {
                float4 A = *(const float4*)(a0 + b4);
                float4 P = *(const float4*)(p0 + b4);
                float4 C = *(const float4*)(cc + b4);
                float4 X = *(const float4*)(r1 + b4);
                float4 Y = *(const float4*)(r2 + b4);
                float Rx = fminf(X.x, Y.x), Ry = fminf(X.y, Y.y);
                float Rz = fminf(X.z, Y.z), Rw = fminf(X.w, Y.w);
                me = fmaxf(me, fmaxf(fmaxf(C.x + fminf(A.x, Rx), C.y + fminf(A.y, Ry)),
                                     fmaxf(C.z + fminf(A.z, Rz), C.w + fminf(A.w, Rw))));
                mo = fmaxf(mo, fmaxf(fmaxf(C.x + fminf(P.x, Rx), C.y + fminf(P.y, Ry)),
                                     fmaxf(C.z + fminf(P.z, Rz), C.w + fminf(P.w, Rw))));
            }
        } else {
#pragma unroll 4
            for (int b4 = 0; b4 < BDIM; b4 += 4) {
                float4 A = *(const float4*)(a0 + b4);
                float4 P = *(const float4*)(p0 + b4);
                float4 C = *(const float4*)(cc + b4);
                me = fmaxf(me, fmaxf(fmaxf(C.x + A.x, C.y + A.y),
                                     fmaxf(C.z + A.z, C.w + A.w)));
                mo = fmaxf(mo, fmaxf(fmaxf(C.x + P.x, C.y + P.y),
                                     fmaxf(C.z + P.z, C.w + P.w)));
            }
        }
        g_m[(size_t)(2 * tau) * TDIM + t] = me;
        g_m[(size_t)(2 * tau + 1) * TDIM + t] = mo;
        g_mp[(size_t)(2 * tau) * TDIM + t] = pack2(me);
        g_mp[(size_t)(2 * tau + 1) * TDIM + t] = pack2(mo);
        if (me > 0.f) atomicMin(&sjs, 2 * tau);
        else if (mo > 0.f) atomicMin(&sjs, 2 * tau + 1);
    }
    __syncthreads();
    if (tid == 0) g_js[t] = sjs;
}

// ---------------- K4: GEMM (R14 shape) + triangle-skip + staggered s -----
// CTA = (128 t-rows tile) x (batch b). 256 threads: 8 rows x 8 cols.
__global__ __launch_bounds__(256, 2) void k_gemm(const float* __restrict__ v1,
                                                 const float* __restrict__ v2,
                                                 float* __restrict__ out) {
    int b = blockIdx.x;
    int tile = 3 - blockIdx.y;  // heavy tiles first
    int t0 = tile * 128;
    int tid = threadIdx.x;
    int rg = tid >> 4, cg = tid & 15;
    int r0 = rg * 8, e0 = cg * 8;

    __shared__ float sV[2][16][EDIM];   // 16 KB
    __shared__ ull sMp[2][16][128];     // 32 KB

    ull acc[8][4];
#pragma unroll
    for (int i = 0; i < 8; ++i)
#pragma unroll
        for (int j = 0; j < 4; ++j) acc[i][j] = 0ull;

    int nst = 16 * (tile + 1);

    int vs = tid >> 5, ve = (tid & 31) * 4;
    int ws = tid >> 6, wt = (tid & 63) * 2;
    int wid = tid >> 5;
    int srot = wid * 2;                          // stagger LDS bursts per warp
    int jwmax = 2 * (t0 + wid * 16 + 15) + 1;    // warp's max useful j

    float4 rv[2];
    ulonglong2 rw[4];

    auto load_stage = [&](int st) {
        int j0 = st * 16;
#pragma unroll
        for (int k = 0; k < 2; ++k) {
            int s = vs + k * 8;
            int j = j0 + s;
            const float* src = (j & 1) ? v2 : v1;
            rv[k] = *(const float4*)&src[((size_t)(j >> 1) * BDIM + b) * EDIM + ve];
        }
#pragma unroll
        for (int k = 0; k < 4; ++k) {
            int s = ws + k * 4;
            rw[k] = *(const ulonglong2*)&g_mp[(size_t)(j0 + s) * TDIM + t0 + wt];
        }
    };
    auto store_stage = [&](int bf) {
#pragma unroll
        for (int k = 0; k < 2; ++k)
            *(float4*)&sV[bf][vs + k * 8][ve] = rv[k];
#pragma unroll
        for (int k = 0; k < 4; ++k)
            *(ulonglong2*)&sMp[bf][ws + k * 4][wt] = rw[k];
    };

    load_stage(0);
    for (int st = 0; st < nst; ++st) {
        int bf = st & 1;
        store_stage(bf);
        __syncthreads();
        if (st + 1 < nst) load_stage(st + 1);
        if (st * 16 <= jwmax) {  // triangle skip: warp has nonzero weights
#pragma unroll
            for (int si = 0; si < 16; ++si) {
                int s = (si + srot) & 15;
                ulonglong2 vv0 = *(const ulonglong2*)&sV[bf][s][e0];
                ulonglong2 vv1 = *(const ulonglong2*)&sV[bf][s][e0 + 4];
                ull va0 = vv0.x, va1 = vv0.y, va2 = vv1.x, va3 = vv1.y;
#pragma unroll
                for (int h = 0; h < 4; ++h) {
                    ulonglong2 wp = *(const ulonglong2*)&sMp[bf][s][r0 + 2 * h];
                    acc[2 * h][0] = ffma2(wp.x, va0, acc[2 * h][0]);
                    acc[2 * h][1] = ffma2(wp.x, va1, acc[2 * h][1]);
                    acc[2 * h][2] = ffma2(wp.x, va2, acc[2 * h][2]);
                    acc[2 * h][3] = ffma2(wp.x, va3, acc[2 * h][3]);
                    acc[2 * h + 1][0] = ffma2(wp.y, va0, acc[2 * h + 1][0]);
                    acc[2 * h + 1][1] = ffma2(wp.y, va1, acc[2 * h + 1][1]);
                    acc[2 * h + 1][2] = ffma2(wp.y, va2, acc[2 * h + 1][2]);
                    acc[2 * h + 1][3] = ffma2(wp.y, va3, acc[2 * h + 1][3]);
                }
            }
        }
    }

    // ---- fused banded correction + store: out = acc - relu(m - s_b) * V ----
    const float* Pb = g_P + (size_t)b * PBSTRIDE;
    const float* t0b = g_t0T + (size_t)b * TDIM;
    const float* tpb = g_TPT + (size_t)b * TDIM;

#pragma unroll
    for (int i = 0; i < 8; ++i) {
        int t = t0 + r0 + i;
        float r[8];
#pragma unroll
        for (int j = 0; j < 4; ++j) unpack2(acc[i][j], r[2 * j], r[2 * j + 1]);

        int js = g_js[t];
        int tau0 = js >> 1;
        for (int tau = tau0; tau <= t; ++tau) {
            int n = t - tau;
            float R;
            if (n) {
                int k = 31 - __clz(n);
                R = fminf(Pb[k * TDIM + tau], Pb[k * TDIM + t - (1 << k)]);
            } else {
                R = INFV;
            }
            float Ca = fminf(t0b[tau], R);
            float Cp = fminf(tpb[tau], R);
            float Cm1 = tau ? fminf(tpb[tau - 1], fminf(Pb[tau - 1], R)) : 0.f;
            float s0 = Ca - Cm1;
            float s1 = Cp - Ca;
            float m0 = g_m[(size_t)(2 * tau) * TDIM + t];
            float m1 = g_m[(size_t)(2 * tau + 1) * TDIM + t];
            float c0 = fmaxf(m0 - s0, 0.f);
            float c1 = fmaxf(m1 - s1, 0.f);
            if (c0 > 0.f || c1 > 0.f) {
                const float* v1p = v1 + ((size_t)tau * BDIM + b) * EDIM + e0;
                const float* v2p = v2 + ((size_t)tau * BDIM + b) * EDIM + e0;
                float4 a0 = *(const float4*)v1p;
                float4 a1 = *(const float4*)(v1p + 4);
                float4 p0 = *(const float4*)v2p;
                float4 p1 = *(const float4*)(v2p + 4);
                r[0] -= c0 * a0.x + c1 * p0.x;
                r[1] -= c0 * a0.y + c1 * p0.y;
                r[2] -= c0 * a0.z + c1 * p0.z;
                r[3] -= c0 * a0.w + c1 * p0.w;
                r[4] -= c0 * a1.x + c1 * p1.x;
                r[5] -= c0 * a1.y + c1 * p1.y;
                r[6] -= c0 * a1.z + c1 * p1.z;
                r[7] -= c0 * a1.w + c1 * p1.w;
            }
        }

        size_t basei = ((size_t)t * BDIM + b) * EDIM + e0;
        *reinterpret_cast<float4*>(out + basei) = make_float4(r[0], r[1], r[2], r[3]);
        *reinterpret_cast<float4*>(out + basei + 4) = make_float4(r[4], r[5], r[6], r[7]);
    }
}

extern "C" void kernel_launch(void* const* d_in, const int* in_sizes, int n_in,
                              void* d_out, int out_size) {
    const float* v1 = (const float*)d_in[0];
    const float* v2 = (const float*)d_in[1];
    const float* d1 = (const float*)d_in[2];
    const float* d2 = (const float*)d_in[3];
    const float* u  = (const float*)d_in[4];
    float* out = (float*)d_out;

    k_A<<<NCH, 256>>>(d1, d2, u);         // 1
    k_B<<<BDIM, 256>>>(d1, d2, u);        // 2
    k_m<<<TDIM, 256>>>();                 // 3
    dim3 gm(BDIM, 4);
    k_gemm<<<gm, 256>>>(v1, v2, out);     // 4  <- ncu capture slot
}